// round 3
// baseline (speedup 1.0000x reference)
#include <cuda_runtime.h>

// out[r,k] = 2^-11 * (WHT_2048(concat(x1,x2))[r,k])^2
// (RZ phase is unit-modulus -> cancels under |.|^2; input real -> state real.)
//
// Factorization (all 11 butterfly stages commute):
//   phase-1 regs : bits 7..10   (ownership i = r*128 + t, coalesced LDG)
//   shuffles     : bits 2..4    (lane bits, 3 stages)
//   phase-2 regs : bits 0,1,5,6 (after one linear smem transpose; LDS.128 reads
//                                and STG.128 stores both conflict-free/coalesced)

__global__ __launch_bounds__(256, 6)
void qfl_wht_kernel(const float* __restrict__ x1,
                    const float* __restrict__ x2,
                    float* __restrict__ out)
{
    __shared__ float smem[2][2048];

    const int t    = threadIdx.x & 127;        // thread within the row group
    const int sub  = threadIdx.x >> 7;         // which of the 2 rows in this block
    const int row  = blockIdx.x * 2 + sub;
    const int lane = t & 31;
    float* s = smem[sub];

    // ---- Phase 1: load, ownership i = r*128 + t (bits 7..10 in regs) ------
    float v[16];
    const float* b1 = x1 + (size_t)row * 1024 + t;
    const float* b2 = x2 + (size_t)row * 1024 + t;
#pragma unroll
    for (int r = 0; r < 8; ++r) v[r]     = __ldg(b1 + r * 128);
#pragma unroll
    for (int r = 0; r < 8; ++r) v[8 + r] = __ldg(b2 + r * 128);

    // butterflies on bits 7..10 (the r index)
#pragma unroll
    for (int b = 0; b < 4; ++b) {
        const int m = 1 << b;
#pragma unroll
        for (int r = 0; r < 16; ++r) {
            if ((r & m) == 0) {
                float a = v[r], c = v[r | m];
                v[r]     = a + c;
                v[r | m] = a - c;
            }
        }
    }

    // ---- Shuffle butterflies on i bits 2,3,4 (= lane bits 2..4) -----------
#pragma unroll
    for (int sb = 2; sb <= 4; ++sb) {
        const int m = 1 << sb;
        const float sgn = (lane & m) ? -1.0f : 1.0f;
#pragma unroll
        for (int r = 0; r < 16; ++r) {
            float w = __shfl_xor_sync(0xffffffffu, v[r], m);
            v[r] = fmaf(sgn, v[r], w);     // up-lane: w - v ; down-lane: v + w
        }
    }

    // ---- Linear smem transpose (writes lane-coalesced -> conflict-free) ---
#pragma unroll
    for (int r = 0; r < 16; ++r) s[r * 128 + t] = v[r];
    __syncthreads();

    // ---- Phase 2 ownership: bits 0,1 (in float4), bits 5,6 (q index),
    //      thread bits = {2,3,4} (t&7) and {7..10} (t>>3).
    const int hi = (t >> 3) * 128;
    const int lo = (t & 7) * 4;
    float4 u[4];
#pragma unroll
    for (int q = 0; q < 4; ++q)
        u[q] = *(const float4*)&s[hi + (q >> 1) * 64 + (q & 1) * 32 + lo];
        // 8-lane LDS.128 phases hit 8 distinct float4 columns -> conflict-free

    // butterflies on bits 0 and 1 (inside each float4)
#pragma unroll
    for (int q = 0; q < 4; ++q) {
        float a0 = u[q].x, a1 = u[q].y, a2 = u[q].z, a3 = u[q].w;
        float p0 = a0 + a1, p1 = a0 - a1;      // bit 0
        float p2 = a2 + a3, p3 = a2 - a3;
        u[q].x = p0 + p2;  u[q].z = p0 - p2;   // bit 1
        u[q].y = p1 + p3;  u[q].w = p1 - p3;
    }

    // butterfly on bit 5 (q bit 0): pairs (0,1) and (2,3)
#pragma unroll
    for (int qq = 0; qq < 4; qq += 2) {
        float4 a = u[qq], c = u[qq + 1];
        u[qq]     = make_float4(a.x + c.x, a.y + c.y, a.z + c.z, a.w + c.w);
        u[qq + 1] = make_float4(a.x - c.x, a.y - c.y, a.z - c.z, a.w - c.w);
    }
    // butterfly on bit 6 (q bit 1): pairs (0,2) and (1,3)
#pragma unroll
    for (int qq = 0; qq < 2; ++qq) {
        float4 a = u[qq], c = u[qq + 2];
        u[qq]     = make_float4(a.x + c.x, a.y + c.y, a.z + c.z, a.w + c.w);
        u[qq + 2] = make_float4(a.x - c.x, a.y - c.y, a.z - c.z, a.w - c.w);
    }

    // ---- Square, scale, coalesced STG.128 ---------------------------------
    const float scale = 1.0f / 2048.0f;
    float* orow = out + (size_t)row * 2048;
#pragma unroll
    for (int q = 0; q < 4; ++q) {
        float4 w = u[q];
        w.x = w.x * w.x * scale;
        w.y = w.y * w.y * scale;
        w.z = w.z * w.z * scale;
        w.w = w.w * w.w * scale;
        *(float4*)&orow[hi + (q >> 1) * 64 + (q & 1) * 32 + lo] = w;
    }
}

extern "C" void kernel_launch(void* const* d_in, const int* in_sizes, int n_in,
                              void* d_out, int out_size)
{
    const float* x1 = (const float*)d_in[0];   // (8192, 1024) f32
    const float* x2 = (const float*)d_in[1];   // (8192, 1024) f32
    float* out = (float*)d_out;                // (8192, 2048) f32

    const int rows = in_sizes[0] / 1024;       // 8192
    qfl_wht_kernel<<<rows / 2, 256>>>(x1, x2, out);
}